// round 15
// baseline (speedup 1.0000x reference)
#include <cuda_runtime.h>
#include <cuda_bf16.h>
#include <stdint.h>
#include <math.h>

#define N_NODES 50000
#define N_EDGES 800000
#define FEAT 256
#define HID 256
#define OUT 40
#define N_BATCH 10000

#define NB_SCAN ((N_NODES + 255) / 256)   // 196 scan blocks

// ---------------- scratch (device globals; no allocation allowed) ----------------
__device__ float g_h1[N_NODES * HID];
__device__ float g_x1[N_NODES * HID];
__device__ float g_h2[N_NODES * OUT];
__device__ float g_x2[N_NODES * OUT];
__device__ float g_sum1[HID], g_sq1[HID], g_scale1[HID], g_shift1[HID];
__device__ float g_sum2[OUT], g_sq2[OUT], g_scale2[OUT], g_shift2[OUT];
__device__ int   g_is64;

// CSR
__device__ int g_cnt[N_NODES];
__device__ int g_off[N_NODES];
__device__ int g_cur[N_NODES];
__device__ int g_csr_src[N_EDGES];
__device__ int g_bsum[NB_SCAN];
__device__ int g_boff[NB_SCAN];

// bf16-split fragment-major weights
__device__ uint2 g_w_hi[16 * 32 * 32];       // W1: [ktile][ntile][lane]
__device__ uint2 g_w_lo[16 * 32 * 32];
__device__ uint2 g_w2_hi[16 * 5 * 32];       // W2
__device__ uint2 g_w2_lo[16 * 5 * 32];

// ---------------- detect dtype + zero accumulators (merged) ----------------------
__global__ void detect_zero_kernel(const void* ei) {
    int i = blockIdx.x * 256 + threadIdx.x;
    if (i == 0) {
        const long long* p = (const long long*)ei;
        int ok64 = 1;
        for (int j = 0; j < 64; j++) {
            long long v = p[j];
            if (v < 0 || v >= (long long)N_NODES) { ok64 = 0; break; }
        }
        g_is64 = ok64;
    }
    if (i < N_NODES) g_cnt[i] = 0;
    if (i < HID) { g_sum1[i] = 0.f; g_sq1[i] = 0.f; }
    if (i < OUT) { g_sum2[i] = 0.f; g_sq2[i] = 0.f; }
}

__device__ __forceinline__ int load_idx(const void* p, long i) {
    return g_is64 ? (int)((const long long*)p)[i] : ((const int*)p)[i];
}

// ---------------- CSR build ------------------------------------------------------
__global__ void hist_kernel(const void* __restrict__ ei) {
    int i = blockIdx.x * 256 + threadIdx.x;
    if (i >= N_EDGES) return;
    int dst = load_idx(ei, (long)N_EDGES + i);
    atomicAdd(&g_cnt[dst], 1);
}

__global__ void scan1_kernel() {
    int i = blockIdx.x * 256 + threadIdx.x;
    int v = (i < N_NODES) ? g_cnt[i] : 0;
    #pragma unroll
    for (int o = 16; o > 0; o >>= 1) v += __shfl_xor_sync(0xffffffffu, v, o);
    __shared__ int ws[8];
    if ((threadIdx.x & 31) == 0) ws[threadIdx.x >> 5] = v;
    __syncthreads();
    if (threadIdx.x == 0) {
        int s = 0;
        #pragma unroll
        for (int j = 0; j < 8; j++) s += ws[j];
        g_bsum[blockIdx.x] = s;
    }
}

__global__ void scan2_kernel() {
    __shared__ int sm[256];
    int t = threadIdx.x;
    int v = (t < NB_SCAN) ? g_bsum[t] : 0;
    sm[t] = v;
    __syncthreads();
    for (int o = 1; o < 256; o <<= 1) {
        int u = (t >= o) ? sm[t - o] : 0;
        __syncthreads();
        sm[t] += u;
        __syncthreads();
    }
    if (t < NB_SCAN) g_boff[t] = sm[t] - v;   // exclusive
}

__global__ void scan3_kernel() {
    int i = blockIdx.x * 256 + threadIdx.x;
    int lane = threadIdx.x & 31, wid = threadIdx.x >> 5;
    int v = (i < N_NODES) ? g_cnt[i] : 0;
    int x = v;
    #pragma unroll
    for (int o = 1; o < 32; o <<= 1) {
        int u = __shfl_up_sync(0xffffffffu, x, o);
        if (lane >= o) x += u;
    }
    __shared__ int wt[8];
    if (lane == 31) wt[wid] = x;
    __syncthreads();
    if (threadIdx.x < 8) {
        int y = wt[threadIdx.x];
        int z = y;
        #pragma unroll
        for (int o = 1; o < 8; o <<= 1) {
            int u = __shfl_up_sync(0xffu, z, o);
            if (threadIdx.x >= o) z += u;
        }
        wt[threadIdx.x] = z - y;
    }
    __syncthreads();
    int excl = x - v + wt[wid] + g_boff[blockIdx.x];
    if (i < N_NODES) { g_off[i] = excl; g_cur[i] = excl; }
}

__global__ void scatter_kernel(const void* __restrict__ ei) {
    int i = blockIdx.x * 256 + threadIdx.x;
    if (i >= N_EDGES) return;
    int src = load_idx(ei, i);
    int dst = load_idx(ei, (long)N_EDGES + i);
    int pos = atomicAdd(&g_cur[dst], 1);
    g_csr_src[pos] = src;
}

// ---------------- bf16 split helpers ----------------------------------------------
__device__ __forceinline__ void split2(float x, float y, unsigned int& h, unsigned int& l) {
    __nv_bfloat162 hb = __floats2bfloat162_rn(x, y);
    float rx = x - __bfloat162float(hb.x);
    float ry = y - __bfloat162float(hb.y);
    __nv_bfloat162 lb = __floats2bfloat162_rn(rx, ry);
    h = *reinterpret_cast<unsigned int*>(&hb);
    l = *reinterpret_cast<unsigned int*>(&lb);
}

// ---------------- prep W1 / W2 -> fragment-major bf16 hi/lo ------------------------
__global__ void prepW_kernel(const float* __restrict__ W) {
    int gid = blockIdx.x * 256 + threadIdx.x;
    if (gid >= 16 * 32 * 32) return;
    int lane = gid & 31;
    int tile = gid >> 5;
    int nt = tile & 31, kt = tile >> 5;
    int g = lane >> 2, i = lane & 3;
    int k0 = kt * 16 + 2 * i;
    int n = nt * 8 + g;
    float b00 = W[(long)k0 * HID + n];
    float b01 = W[(long)(k0 + 1) * HID + n];
    float b10 = W[(long)(k0 + 8) * HID + n];
    float b11 = W[(long)(k0 + 9) * HID + n];
    uint2 hi, lo;
    split2(b00, b01, hi.x, lo.x);
    split2(b10, b11, hi.y, lo.y);
    g_w_hi[gid] = hi;
    g_w_lo[gid] = lo;
}

__global__ void prepW2_kernel(const float* __restrict__ W) {
    int gid = blockIdx.x * 256 + threadIdx.x;
    if (gid >= 16 * 5 * 32) return;
    int lane = gid & 31;
    int tile = gid >> 5;
    int nt = tile % 5, kt = tile / 5;
    int g = lane >> 2, i = lane & 3;
    int k0 = kt * 16 + 2 * i;
    int n = nt * 8 + g;
    float b00 = W[(long)k0 * OUT + n];
    float b01 = W[(long)(k0 + 1) * OUT + n];
    float b10 = W[(long)(k0 + 8) * OUT + n];
    float b11 = W[(long)(k0 + 9) * OUT + n];
    uint2 hi, lo;
    split2(b00, b01, hi.x, lo.x);
    split2(b10, b11, hi.y, lo.y);
    g_w2_hi[gid] = hi;
    g_w2_lo[gid] = lo;
}

#define MMA_BF16(c, a, b)                                                      \
    asm volatile("mma.sync.aligned.m16n8k16.row.col.f32.bf16.bf16.f32 "        \
                 "{%0,%1,%2,%3}, {%4,%5,%6,%7}, {%8,%9}, {%0,%1,%2,%3};"       \
                 : "+f"((c)[0]), "+f"((c)[1]), "+f"((c)[2]), "+f"((c)[3])      \
                 : "r"((a).x), "r"((a).y), "r"((a).z), "r"((a).w),             \
                   "r"((b).x), "r"((b).y))

// ---------------- GEMM1 (tensor cores, inline A split): h1 = A @ W1 + b1 ----------
__global__ __launch_bounds__(256) void gemm1_tc_kernel(
    const float* __restrict__ A, const float* __restrict__ bias)
{
    const int w = threadIdx.x >> 5, lane = threadIdx.x & 31;
    const int wm = w & 1, wn = w >> 1;
    const int g = lane >> 2, i = lane & 3;
    const int m_base = blockIdx.x * 128 + wm * 64;
    const int nt0 = blockIdx.y * 16 + wn * 4;

    float acc[4][4][4];
    #pragma unroll
    for (int mi = 0; mi < 4; mi++)
        #pragma unroll
        for (int ni = 0; ni < 4; ni++)
            #pragma unroll
            for (int r = 0; r < 4; r++) acc[mi][ni][r] = 0.f;

    #pragma unroll 1
    for (int kt = 0; kt < 16; kt++) {
        const int c0 = kt * 16 + 2 * i;

        uint2 bh[4], bl[4];
        #pragma unroll
        for (int ni = 0; ni < 4; ni++) {
            int t = (kt * 32 + nt0 + ni) * 32 + lane;
            bh[ni] = g_w_hi[t];
            bl[ni] = g_w_lo[t];
        }

        uint4 ah[4], al[4];
        #pragma unroll
        for (int mi = 0; mi < 4; mi++) {
            int r0 = min(m_base + mi * 16 + g, N_NODES - 1);
            int r1 = min(m_base + mi * 16 + g + 8, N_NODES - 1);
            const float* p0 = A + (long)r0 * FEAT + c0;
            const float* p1 = A + (long)r1 * FEAT + c0;
            float2 u0 = *(const float2*)p0;
            float2 u2 = *(const float2*)(p0 + 8);
            float2 u1 = *(const float2*)p1;
            float2 u3 = *(const float2*)(p1 + 8);
            split2(u0.x, u0.y, ah[mi].x, al[mi].x);
            split2(u1.x, u1.y, ah[mi].y, al[mi].y);
            split2(u2.x, u2.y, ah[mi].z, al[mi].z);
            split2(u3.x, u3.y, ah[mi].w, al[mi].w);
        }

        #pragma unroll
        for (int mi = 0; mi < 4; mi++)
            #pragma unroll
            for (int ni = 0; ni < 4; ni++) {
                MMA_BF16(acc[mi][ni], ah[mi], bh[ni]);
                MMA_BF16(acc[mi][ni], ah[mi], bl[ni]);
                MMA_BF16(acc[mi][ni], al[mi], bh[ni]);
            }
    }

    #pragma unroll
    for (int mi = 0; mi < 4; mi++) {
        int r0 = m_base + mi * 16 + g;
        int r1 = r0 + 8;
        #pragma unroll
        for (int ni = 0; ni < 4; ni++) {
            int c = (nt0 + ni) * 8 + 2 * i;
            float bx = bias[c], by = bias[c + 1];
            if (r0 < N_NODES) {
                float2 o = make_float2(acc[mi][ni][0] + bx, acc[mi][ni][1] + by);
                *(float2*)&g_h1[(long)r0 * HID + c] = o;
            }
            if (r1 < N_NODES) {
                float2 o = make_float2(acc[mi][ni][2] + bx, acc[mi][ni][3] + by);
                *(float2*)&g_h1[(long)r1 * HID + c] = o;
            }
        }
    }
}

// ---------------- Layer-1 aggregation: CSR, warp-per-node, cp.async depth-3 -------
// Per-warp 4-slot smem ring (1 KB/slot). Each edge's src row is fetched by two
// 16B cp.async per lane into slot (e&3); one commit_group per stage (empty groups
// pad the tail so wait_group 3 accounting is uniform; stale pending groups at node
// boundaries are always empty). Lane i consumes exactly the bytes it copied.
__global__ __launch_bounds__(256) void agg1_kernel(const float* __restrict__ gamma) {
    __shared__ float4 ring[8][4][64];   // 32 KB
    __shared__ float sm_s[HID], sm_q[HID];

    const int wid = threadIdx.x >> 5;
    const int lane = threadIdx.x & 31;
    const int gwarp = (blockIdx.x * 256 + threadIdx.x) >> 5;
    const int nwarps = gridDim.x * 8;
    const float gam = gamma[0];

    unsigned int rb0[4], rb1[4];
    #pragma unroll
    for (int s = 0; s < 4; s++) {
        rb0[s] = (unsigned int)__cvta_generic_to_shared(&ring[wid][s][lane]);
        rb1[s] = (unsigned int)__cvta_generic_to_shared(&ring[wid][s][lane + 32]);
    }

    float ps0[4] = {0, 0, 0, 0}, ps1[4] = {0, 0, 0, 0};
    float pq0[4] = {0, 0, 0, 0}, pq1[4] = {0, 0, 0, 0};

    for (int node = gwarp; node < N_NODES; node += nwarps) {
        const float4* hd = (const float4*)(g_h1 + (long)node * HID);
        float4 d0 = hd[lane], d1 = hd[lane + 32];
        float4 a0 = make_float4(0.f, 0.f, 0.f, 0.f);
        float4 a1 = make_float4(0.f, 0.f, 0.f, 0.f);
        float den = 0.f;
        const int beg = g_off[node];
        const int cnt = g_cnt[node];

        // prologue: stages 0..2 (empty groups if beyond cnt)
        #pragma unroll
        for (int p = 0; p < 3; p++) {
            if (p < cnt) {
                const float* hp = g_h1 + (long)g_csr_src[beg + p] * HID;
                asm volatile("cp.async.ca.shared.global [%0], [%1], 16;"
                             :: "r"(rb0[p]), "l"(hp + 4 * lane) : "memory");
                asm volatile("cp.async.ca.shared.global [%0], [%1], 16;"
                             :: "r"(rb1[p]), "l"(hp + 128 + 4 * lane) : "memory");
            }
            asm volatile("cp.async.commit_group;" ::: "memory");
        }

        for (int e = 0; e < cnt; e++) {
            // issue stage e+3 (or empty group)
            int f = e + 3;
            if (f < cnt) {
                int s = f & 3;
                const float* hp = g_h1 + (long)g_csr_src[beg + f] * HID;
                asm volatile("cp.async.ca.shared.global [%0], [%1], 16;"
                             :: "r"(rb0[s]), "l"(hp + 4 * lane) : "memory");
                asm volatile("cp.async.ca.shared.global [%0], [%1], 16;"
                             :: "r"(rb1[s]), "l"(hp + 128 + 4 * lane) : "memory");
            }
            asm volatile("cp.async.commit_group;" ::: "memory");
            // ensure stage e complete (keep newest 3 groups in flight)
            asm volatile("cp.async.wait_group 3;" ::: "memory");

            int s = e & 3;
            float4 c0 = ring[wid][s][lane];
            float4 c1 = ring[wid][s][lane + 32];

            float dx = c0.x - d0.x; float d2 = dx * dx;
            dx = c0.y - d0.y; d2 = fmaf(dx, dx, d2);
            dx = c0.z - d0.z; d2 = fmaf(dx, dx, d2);
            dx = c0.w - d0.w; d2 = fmaf(dx, dx, d2);
            dx = c1.x - d1.x; d2 = fmaf(dx, dx, d2);
            dx = c1.y - d1.y; d2 = fmaf(dx, dx, d2);
            dx = c1.z - d1.z; d2 = fmaf(dx, dx, d2);
            dx = c1.w - d1.w; d2 = fmaf(dx, dx, d2);
            #pragma unroll
            for (int o = 16; o > 0; o >>= 1) d2 += __shfl_xor_sync(0xffffffffu, d2, o);
            float w = __expf(-gam * d2);
            a0.x = fmaf(w, c0.x, a0.x); a0.y = fmaf(w, c0.y, a0.y);
            a0.z = fmaf(w, c0.z, a0.z); a0.w = fmaf(w, c0.w, a0.w);
            a1.x = fmaf(w, c1.x, a1.x); a1.y = fmaf(w, c1.y, a1.y);
            a1.z = fmaf(w, c1.z, a1.z); a1.w = fmaf(w, c1.w, a1.w);
            den += w;
        }

        float inv = 1.f / (den + 1e-16f);
        float4 x0 = make_float4(a0.x * inv, a0.y * inv, a0.z * inv, a0.w * inv);
        float4 x1 = make_float4(a1.x * inv, a1.y * inv, a1.z * inv, a1.w * inv);
        float4* xp = (float4*)(g_x1 + (long)node * HID);
        xp[lane] = x0; xp[lane + 32] = x1;
        ps0[0] += x0.x; ps0[1] += x0.y; ps0[2] += x0.z; ps0[3] += x0.w;
        ps1[0] += x1.x; ps1[1] += x1.y; ps1[2] += x1.z; ps1[3] += x1.w;
        pq0[0] += x0.x * x0.x; pq0[1] += x0.y * x0.y; pq0[2] += x0.z * x0.z; pq0[3] += x0.w * x0.w;
        pq1[0] += x1.x * x1.x; pq1[1] += x1.y * x1.y; pq1[2] += x1.z * x1.z; pq1[3] += x1.w * x1.w;
    }

    sm_s[threadIdx.x] = 0.f; sm_q[threadIdx.x] = 0.f;
    __syncthreads();
    #pragma unroll
    for (int j = 0; j < 4; j++) {
        atomicAdd(&sm_s[4 * lane + j], ps0[j]);
        atomicAdd(&sm_s[128 + 4 * lane + j], ps1[j]);
        atomicAdd(&sm_q[4 * lane + j], pq0[j]);
        atomicAdd(&sm_q[128 + 4 * lane + j], pq1[j]);
    }
    __syncthreads();
    atomicAdd(&g_sum1[threadIdx.x], sm_s[threadIdx.x]);
    atomicAdd(&g_sq1[threadIdx.x], sm_q[threadIdx.x]);
}

__global__ void bnprep1_kernel(const float* __restrict__ w, const float* __restrict__ b) {
    int c = threadIdx.x;
    float mean = g_sum1[c] * (1.f / N_NODES);
    float var  = g_sq1[c] * (1.f / N_NODES) - mean * mean;
    float sc = w[c] * rsqrtf(var + 1e-5f);
    g_scale1[c] = sc;
    g_shift1[c] = b[c] - mean * sc;
}

// ---------------- GEMM2 (tensor cores): h2 = relu(bn1(x1)) @ W2 + b2 ---------------
__global__ __launch_bounds__(256) void gemm2_tc_kernel(const float* __restrict__ b2) {
    __shared__ float s_sc[HID], s_sh[HID];
    if (threadIdx.x < 128) {
        s_sc[threadIdx.x] = g_scale1[threadIdx.x];
        s_sc[threadIdx.x + 128] = g_scale1[threadIdx.x + 128];
        s_sh[threadIdx.x] = g_shift1[threadIdx.x];
        s_sh[threadIdx.x + 128] = g_shift1[threadIdx.x + 128];
    }
    __syncthreads();

    const int w = threadIdx.x >> 5, lane = threadIdx.x & 31;
    const int g = lane >> 2, i = lane & 3;
    const int m_base = blockIdx.x * 512 + w * 64;

    float acc[4][5][4];
    #pragma unroll
    for (int mi = 0; mi < 4; mi++)
        #pragma unroll
        for (int ni = 0; ni < 5; ni++)
            #pragma unroll
            for (int r = 0; r < 4; r++) acc[mi][ni][r] = 0.f;

    #pragma unroll 1
    for (int kt = 0; kt < 16; kt++) {
        const int c0 = kt * 16 + 2 * i;
        float sc0 = s_sc[c0], sc1 = s_sc[c0 + 1], sc8 = s_sc[c0 + 8], sc9 = s_sc[c0 + 9];
        float sh0 = s_sh[c0], sh1 = s_sh[c0 + 1], sh8 = s_sh[c0 + 8], sh9 = s_sh[c0 + 9];

        uint2 bh[5], bl[5];
        #pragma unroll
        for (int ni = 0; ni < 5; ni++) {
            int t = (kt * 5 + ni) * 32 + lane;
            bh[ni] = g_w2_hi[t];
            bl[ni] = g_w2_lo[t];
        }

        uint4 ah[4], al[4];
        #pragma unroll
        for (int mi = 0; mi < 4; mi++) {
            int r0 = min(m_base + mi * 16 + g, N_NODES - 1);
            int r1 = min(m_base + mi * 16 + g + 8, N_NODES - 1);
            const float* p0 = g_x1 + (long)r0 * HID + c0;
            const float* p1 = g_x1 + (long)r1 * HID + c0;
            float2 u0 = *(const float2*)p0;
            float2 u2 = *(const float2*)(p0 + 8);
            float2 u1 = *(const float2*)p1;
            float2 u3 = *(const float2*)(p1 + 8);
            u0.x = fmaxf(fmaf(u0.x, sc0, sh0), 0.f);
            u0.y = fmaxf(fmaf(u0.y, sc1, sh1), 0.f);
            u1.x = fmaxf(fmaf(u1.x, sc0, sh0), 0.f);
            u1.y = fmaxf(fmaf(u1.y, sc1, sh1), 0.f);
            u2.x = fmaxf(fmaf(u2.x, sc8, sh8), 0.f);
            u2.y = fmaxf(fmaf(u2.y, sc9, sh9), 0.f);
            u3.x = fmaxf(fmaf(u3.x, sc8, sh8), 0.f);
            u3.y = fmaxf(fmaf(u3.y, sc9, sh9), 0.f);
            split2(u0.x, u0.y, ah[mi].x, al[mi].x);
            split2(u1.x, u1.y, ah[mi].y, al[mi].y);
            split2(u2.x, u2.y, ah[mi].z, al[mi].z);
            split2(u3.x, u3.y, ah[mi].w, al[mi].w);
        }

        #pragma unroll
        for (int mi = 0; mi < 4; mi++)
            #pragma unroll
            for (int ni = 0; ni < 5; ni++) {
                MMA_BF16(acc[mi][ni], ah[mi], bh[ni]);
                MMA_BF16(acc[mi][ni], ah[mi], bl[ni]);
                MMA_BF16(acc[mi][ni], al[mi], bh[ni]);
            }
    }

    #pragma unroll
    for (int mi = 0; mi < 4; mi++) {
        int r0 = m_base + mi * 16 + g;
        int r1 = r0 + 8;
        #pragma unroll
        for (int ni = 0; ni < 5; ni++) {
            int c = ni * 8 + 2 * i;
            float bx = b2[c], by = b2[c + 1];
            if (r0 < N_NODES) {
                float2 o = make_float2(acc[mi][ni][0] + bx, acc[mi][ni][1] + by);
                *(float2*)&g_h2[(long)r0 * OUT + c] = o;
            }
            if (r1 < N_NODES) {
                float2 o = make_float2(acc[mi][ni][2] + bx, acc[mi][ni][3] + by);
                *(float2*)&g_h2[(long)r1 * OUT + c] = o;
            }
        }
    }
}

// ---------------- Layer-2 aggregation (prefetch depth 1) --------------------------
__global__ __launch_bounds__(256) void agg2_kernel(const float* __restrict__ gamma) {
    const int lane = threadIdx.x & 31;
    const int gwarp = (blockIdx.x * 256 + threadIdx.x) >> 5;
    const int nwarps = gridDim.x * 8;
    const float gam = gamma[0];

    float ps[2] = {0, 0}, pq[2] = {0, 0};

    for (int node = gwarp; node < N_NODES; node += nwarps) {
        const float2* hd = (const float2*)(g_h2 + (long)node * OUT);
        float2 d = make_float2(0.f, 0.f);
        if (lane < 20) d = hd[lane];
        float2 a = make_float2(0.f, 0.f);
        float den = 0.f;
        const int beg = g_off[node];
        const int cnt = g_cnt[node];

        float2 sv = make_float2(0.f, 0.f);
        if (cnt > 0) {
            int sn = g_csr_src[beg];
            if (lane < 20) sv = ((const float2*)(g_h2 + (long)sn * OUT))[lane];
        }
        for (int e = 0; e < cnt; e++) {
            float2 c = sv;
            if (e + 1 < cnt) {
                int sn = g_csr_src[beg + e + 1];
                if (lane < 20) sv = ((const float2*)(g_h2 + (long)sn * OUT))[lane];
            }
            float dx = c.x - d.x, dy = c.y - d.y;
            float d2 = (lane < 20) ? fmaf(dx, dx, dy * dy) : 0.f;
            #pragma unroll
            for (int o = 16; o > 0; o >>= 1) d2 += __shfl_xor_sync(0xffffffffu, d2, o);
            float w = __expf(-gam * d2);
            a.x = fmaf(w, c.x, a.x); a.y = fmaf(w, c.y, a.y);
            den += w;
        }
        float inv = 1.f / (den + 1e-16f);
        float2 x = make_float2(a.x * inv, a.y * inv);
        if (lane < 20) {
            ((float2*)(g_x2 + (long)node * OUT))[lane] = x;
            ps[0] += x.x; ps[1] += x.y;
            pq[0] += x.x * x.x; pq[1] += x.y * x.y;
        }
    }

    __shared__ float sm_s[OUT], sm_q[OUT];
    if (threadIdx.x < OUT) { sm_s[threadIdx.x] = 0.f; sm_q[threadIdx.x] = 0.f; }
    __syncthreads();
    if (lane < 20) {
        atomicAdd(&sm_s[2 * lane + 0], ps[0]);
        atomicAdd(&sm_s[2 * lane + 1], ps[1]);
        atomicAdd(&sm_q[2 * lane + 0], pq[0]);
        atomicAdd(&sm_q[2 * lane + 1], pq[1]);
    }
    __syncthreads();
    if (threadIdx.x < OUT) {
        atomicAdd(&g_sum2[threadIdx.x], sm_s[threadIdx.x]);
        atomicAdd(&g_sq2[threadIdx.x], sm_q[threadIdx.x]);
    }
}

__global__ void bnprep2_kernel(const float* __restrict__ w, const float* __restrict__ b) {
    int c = threadIdx.x;
    float mean = g_sum2[c] * (1.f / N_NODES);
    float var  = g_sq2[c] * (1.f / N_NODES) - mean * mean;
    float sc = w[c] * rsqrtf(var + 1e-5f);
    g_scale2[c] = sc;
    g_shift2[c] = b[c] - mean * sc;
}

// ---------------- gather batch nodes, BN2 + relu + log_softmax -------------------
__global__ __launch_bounds__(256) void final_kernel(
    const void* __restrict__ bnodes, float* __restrict__ out)
{
    int warp = (blockIdx.x * 256 + threadIdx.x) >> 5;
    int lane = threadIdx.x & 31;
    if (warp >= N_BATCH) return;
    int node = load_idx(bnodes, warp);
    const float* x = g_x2 + (long)node * OUT;

    float v0 = fmaxf(fmaf(x[lane], g_scale2[lane], g_shift2[lane]), 0.f);
    float v1 = -1e30f;
    if (lane < 8)
        v1 = fmaxf(fmaf(x[32 + lane], g_scale2[32 + lane], g_shift2[32 + lane]), 0.f);

    float m = fmaxf(v0, v1);
    #pragma unroll
    for (int o = 16; o > 0; o >>= 1) m = fmaxf(m, __shfl_xor_sync(0xffffffffu, m, o));
    float e = expf(v0 - m) + (lane < 8 ? expf(v1 - m) : 0.f);
    #pragma unroll
    for (int o = 16; o > 0; o >>= 1) e += __shfl_xor_sync(0xffffffffu, e, o);
    float lz = m + logf(e);

    out[(long)warp * OUT + lane] = v0 - lz;
    if (lane < 8) out[(long)warp * OUT + 32 + lane] = v1 - lz;
}

// ---------------- launcher --------------------------------------------------------
extern "C" void kernel_launch(void* const* d_in, const int* in_sizes, int n_in,
                              void* d_out, int out_size) {
    const float* features = (const float*)d_in[0];
    const void*  edge     = d_in[1];
    const void*  batch    = d_in[2];
    const float* W1 = (const float*)d_in[3];
    const float* b1 = (const float*)d_in[4];
    const float* g1 = (const float*)d_in[5];
    const float* W2 = (const float*)d_in[6];
    const float* b2 = (const float*)d_in[7];
    const float* g2 = (const float*)d_in[8];
    const float* bn1w = (const float*)d_in[9];
    const float* bn1b = (const float*)d_in[10];
    const float* bn2w = (const float*)d_in[11];
    const float* bn2b = (const float*)d_in[12];
    float* out = (float*)d_out;

    static cudaStream_t s2 = 0;
    static cudaEvent_t ev_fork = 0, ev_join = 0;
    if (!s2) {
        cudaStreamCreateWithFlags(&s2, cudaStreamNonBlocking);
        cudaEventCreateWithFlags(&ev_fork, cudaEventDisableTiming);
        cudaEventCreateWithFlags(&ev_join, cudaEventDisableTiming);
    }

    detect_zero_kernel<<<NB_SCAN, 256>>>(edge);
    cudaEventRecord(ev_fork, 0);

    // ---- side stream: CSR build ----
    cudaStreamWaitEvent(s2, ev_fork, 0);
    hist_kernel<<<(N_EDGES + 255) / 256, 256, 0, s2>>>(edge);
    scan1_kernel<<<NB_SCAN, 256, 0, s2>>>();
    scan2_kernel<<<1, 256, 0, s2>>>();
    scan3_kernel<<<NB_SCAN, 256, 0, s2>>>();
    scatter_kernel<<<(N_EDGES + 255) / 256, 256, 0, s2>>>(edge);
    cudaEventRecord(ev_join, s2);

    // ---- main stream: weight prep + GEMM1 ----
    prepW_kernel<<<(16 * 32 * 32 + 255) / 256, 256>>>(W1);
    prepW2_kernel<<<(16 * 5 * 32 + 255) / 256, 256>>>(W2);
    dim3 gg1((N_NODES + 127) / 128, 2);
    gemm1_tc_kernel<<<gg1, 256>>>(features, b1);

    cudaStreamWaitEvent(0, ev_join, 0);

    agg1_kernel<<<2048, 256>>>(g1);
    bnprep1_kernel<<<1, HID>>>(bn1w, bn1b);

    gemm2_tc_kernel<<<(N_NODES + 511) / 512, 256>>>(b2);
    agg2_kernel<<<1024, 256>>>(g2);
    bnprep2_kernel<<<1, OUT>>>(bn2w, bn2b);

    final_kernel<<<(N_BATCH * 32 + 255) / 256, 256>>>(batch, out);
}

// round 16
// speedup vs baseline: 1.0163x; 1.0163x over previous
#include <cuda_runtime.h>
#include <cuda_bf16.h>
#include <stdint.h>
#include <math.h>

#define N_NODES 50000
#define N_EDGES 800000
#define FEAT 256
#define HID 256
#define OUT 40
#define N_BATCH 10000

#define NB_SCAN ((N_NODES + 255) / 256)   // 196 scan blocks

// ---------------- scratch (device globals; no allocation allowed) ----------------
__device__ float g_h1[N_NODES * HID];
__device__ float g_x1[N_NODES * HID];
__device__ float g_h2[N_NODES * OUT];
__device__ float g_x2[N_NODES * OUT];
__device__ float g_sum1[HID], g_sq1[HID], g_scale1[HID], g_shift1[HID];
__device__ float g_sum2[OUT], g_sq2[OUT], g_scale2[OUT], g_shift2[OUT];
__device__ int   g_is64;

// CSR
__device__ int g_cnt[N_NODES];
__device__ int g_off[N_NODES];
__device__ int g_cur[N_NODES];
__device__ int g_csr_src[N_EDGES];
__device__ int g_bsum[NB_SCAN];
__device__ int g_boff[NB_SCAN];

// bf16-split fragment-major weights
__device__ uint2 g_w_hi[16 * 32 * 32];       // W1: [ktile][ntile][lane]
__device__ uint2 g_w_lo[16 * 32 * 32];
__device__ uint2 g_w2_hi[16 * 5 * 32];       // W2
__device__ uint2 g_w2_lo[16 * 5 * 32];

// ---------------- detect dtype + zero accumulators (merged) ----------------------
__global__ void detect_zero_kernel(const void* ei) {
    int i = blockIdx.x * 256 + threadIdx.x;
    if (i == 0) {
        const long long* p = (const long long*)ei;
        int ok64 = 1;
        for (int j = 0; j < 64; j++) {
            long long v = p[j];
            if (v < 0 || v >= (long long)N_NODES) { ok64 = 0; break; }
        }
        g_is64 = ok64;
    }
    if (i < N_NODES) g_cnt[i] = 0;
    if (i < HID) { g_sum1[i] = 0.f; g_sq1[i] = 0.f; }
    if (i < OUT) { g_sum2[i] = 0.f; g_sq2[i] = 0.f; }
}

__device__ __forceinline__ int load_idx(const void* p, long i) {
    return g_is64 ? (int)((const long long*)p)[i] : ((const int*)p)[i];
}

// ---------------- CSR build ------------------------------------------------------
__global__ void hist_kernel(const void* __restrict__ ei) {
    int i = blockIdx.x * 256 + threadIdx.x;
    if (i >= N_EDGES) return;
    int dst = load_idx(ei, (long)N_EDGES + i);
    atomicAdd(&g_cnt[dst], 1);
}

__global__ void scan1_kernel() {
    int i = blockIdx.x * 256 + threadIdx.x;
    int v = (i < N_NODES) ? g_cnt[i] : 0;
    #pragma unroll
    for (int o = 16; o > 0; o >>= 1) v += __shfl_xor_sync(0xffffffffu, v, o);
    __shared__ int ws[8];
    if ((threadIdx.x & 31) == 0) ws[threadIdx.x >> 5] = v;
    __syncthreads();
    if (threadIdx.x == 0) {
        int s = 0;
        #pragma unroll
        for (int j = 0; j < 8; j++) s += ws[j];
        g_bsum[blockIdx.x] = s;
    }
}

__global__ void scan2_kernel() {
    __shared__ int sm[256];
    int t = threadIdx.x;
    int v = (t < NB_SCAN) ? g_bsum[t] : 0;
    sm[t] = v;
    __syncthreads();
    for (int o = 1; o < 256; o <<= 1) {
        int u = (t >= o) ? sm[t - o] : 0;
        __syncthreads();
        sm[t] += u;
        __syncthreads();
    }
    if (t < NB_SCAN) g_boff[t] = sm[t] - v;   // exclusive
}

__global__ void scan3_kernel() {
    int i = blockIdx.x * 256 + threadIdx.x;
    int lane = threadIdx.x & 31, wid = threadIdx.x >> 5;
    int v = (i < N_NODES) ? g_cnt[i] : 0;
    int x = v;
    #pragma unroll
    for (int o = 1; o < 32; o <<= 1) {
        int u = __shfl_up_sync(0xffffffffu, x, o);
        if (lane >= o) x += u;
    }
    __shared__ int wt[8];
    if (lane == 31) wt[wid] = x;
    __syncthreads();
    if (threadIdx.x < 8) {
        int y = wt[threadIdx.x];
        int z = y;
        #pragma unroll
        for (int o = 1; o < 8; o <<= 1) {
            int u = __shfl_up_sync(0xffu, z, o);
            if (threadIdx.x >= o) z += u;
        }
        wt[threadIdx.x] = z - y;
    }
    __syncthreads();
    int excl = x - v + wt[wid] + g_boff[blockIdx.x];
    if (i < N_NODES) { g_off[i] = excl; g_cur[i] = excl; }
}

__global__ void scatter_kernel(const void* __restrict__ ei) {
    int i = blockIdx.x * 256 + threadIdx.x;
    if (i >= N_EDGES) return;
    int src = load_idx(ei, i);
    int dst = load_idx(ei, (long)N_EDGES + i);
    int pos = atomicAdd(&g_cur[dst], 1);
    g_csr_src[pos] = src;
}

// ---------------- bf16 split helpers ----------------------------------------------
__device__ __forceinline__ void split2(float x, float y, unsigned int& h, unsigned int& l) {
    __nv_bfloat162 hb = __floats2bfloat162_rn(x, y);
    float rx = x - __bfloat162float(hb.x);
    float ry = y - __bfloat162float(hb.y);
    __nv_bfloat162 lb = __floats2bfloat162_rn(rx, ry);
    h = *reinterpret_cast<unsigned int*>(&hb);
    l = *reinterpret_cast<unsigned int*>(&lb);
}

// ---------------- prep W1 / W2 -> fragment-major bf16 hi/lo ------------------------
__global__ void prepW_kernel(const float* __restrict__ W) {
    int gid = blockIdx.x * 256 + threadIdx.x;
    if (gid >= 16 * 32 * 32) return;
    int lane = gid & 31;
    int tile = gid >> 5;
    int nt = tile & 31, kt = tile >> 5;
    int g = lane >> 2, i = lane & 3;
    int k0 = kt * 16 + 2 * i;
    int n = nt * 8 + g;
    float b00 = W[(long)k0 * HID + n];
    float b01 = W[(long)(k0 + 1) * HID + n];
    float b10 = W[(long)(k0 + 8) * HID + n];
    float b11 = W[(long)(k0 + 9) * HID + n];
    uint2 hi, lo;
    split2(b00, b01, hi.x, lo.x);
    split2(b10, b11, hi.y, lo.y);
    g_w_hi[gid] = hi;
    g_w_lo[gid] = lo;
}

__global__ void prepW2_kernel(const float* __restrict__ W) {
    int gid = blockIdx.x * 256 + threadIdx.x;
    if (gid >= 16 * 5 * 32) return;
    int lane = gid & 31;
    int tile = gid >> 5;
    int nt = tile % 5, kt = tile / 5;
    int g = lane >> 2, i = lane & 3;
    int k0 = kt * 16 + 2 * i;
    int n = nt * 8 + g;
    float b00 = W[(long)k0 * OUT + n];
    float b01 = W[(long)(k0 + 1) * OUT + n];
    float b10 = W[(long)(k0 + 8) * OUT + n];
    float b11 = W[(long)(k0 + 9) * OUT + n];
    uint2 hi, lo;
    split2(b00, b01, hi.x, lo.x);
    split2(b10, b11, hi.y, lo.y);
    g_w2_hi[gid] = hi;
    g_w2_lo[gid] = lo;
}

#define MMA_BF16(c, a, b)                                                      \
    asm volatile("mma.sync.aligned.m16n8k16.row.col.f32.bf16.bf16.f32 "        \
                 "{%0,%1,%2,%3}, {%4,%5,%6,%7}, {%8,%9}, {%0,%1,%2,%3};"       \
                 : "+f"((c)[0]), "+f"((c)[1]), "+f"((c)[2]), "+f"((c)[3])      \
                 : "r"((a).x), "r"((a).y), "r"((a).z), "r"((a).w),             \
                   "r"((b).x), "r"((b).y))

// ---------------- GEMM1 (tensor cores, inline A split): h1 = A @ W1 + b1 ----------
__global__ __launch_bounds__(256) void gemm1_tc_kernel(
    const float* __restrict__ A, const float* __restrict__ bias)
{
    const int w = threadIdx.x >> 5, lane = threadIdx.x & 31;
    const int wm = w & 1, wn = w >> 1;
    const int g = lane >> 2, i = lane & 3;
    const int m_base = blockIdx.x * 128 + wm * 64;
    const int nt0 = blockIdx.y * 16 + wn * 4;

    float acc[4][4][4];
    #pragma unroll
    for (int mi = 0; mi < 4; mi++)
        #pragma unroll
        for (int ni = 0; ni < 4; ni++)
            #pragma unroll
            for (int r = 0; r < 4; r++) acc[mi][ni][r] = 0.f;

    #pragma unroll 1
    for (int kt = 0; kt < 16; kt++) {
        const int c0 = kt * 16 + 2 * i;

        uint2 bh[4], bl[4];
        #pragma unroll
        for (int ni = 0; ni < 4; ni++) {
            int t = (kt * 32 + nt0 + ni) * 32 + lane;
            bh[ni] = g_w_hi[t];
            bl[ni] = g_w_lo[t];
        }

        uint4 ah[4], al[4];
        #pragma unroll
        for (int mi = 0; mi < 4; mi++) {
            int r0 = min(m_base + mi * 16 + g, N_NODES - 1);
            int r1 = min(m_base + mi * 16 + g + 8, N_NODES - 1);
            const float* p0 = A + (long)r0 * FEAT + c0;
            const float* p1 = A + (long)r1 * FEAT + c0;
            float2 u0 = *(const float2*)p0;
            float2 u2 = *(const float2*)(p0 + 8);
            float2 u1 = *(const float2*)p1;
            float2 u3 = *(const float2*)(p1 + 8);
            split2(u0.x, u0.y, ah[mi].x, al[mi].x);
            split2(u1.x, u1.y, ah[mi].y, al[mi].y);
            split2(u2.x, u2.y, ah[mi].z, al[mi].z);
            split2(u3.x, u3.y, ah[mi].w, al[mi].w);
        }

        #pragma unroll
        for (int mi = 0; mi < 4; mi++)
            #pragma unroll
            for (int ni = 0; ni < 4; ni++) {
                MMA_BF16(acc[mi][ni], ah[mi], bh[ni]);
                MMA_BF16(acc[mi][ni], ah[mi], bl[ni]);
                MMA_BF16(acc[mi][ni], al[mi], bh[ni]);
            }
    }

    #pragma unroll
    for (int mi = 0; mi < 4; mi++) {
        int r0 = m_base + mi * 16 + g;
        int r1 = r0 + 8;
        #pragma unroll
        for (int ni = 0; ni < 4; ni++) {
            int c = (nt0 + ni) * 8 + 2 * i;
            float bx = bias[c], by = bias[c + 1];
            if (r0 < N_NODES) {
                float2 o = make_float2(acc[mi][ni][0] + bx, acc[mi][ni][1] + by);
                *(float2*)&g_h1[(long)r0 * HID + c] = o;
            }
            if (r1 < N_NODES) {
                float2 o = make_float2(acc[mi][ni][2] + bx, acc[mi][ni][3] + by);
                *(float2*)&g_h1[(long)r1 * HID + c] = o;
            }
        }
    }
}

// ---------------- Layer-1 aggregation: CSR, warp-per-node (prefetch depth 1) ------
__global__ __launch_bounds__(256) void agg1_kernel(const float* __restrict__ gamma) {
    const int lane = threadIdx.x & 31;
    const int gwarp = (blockIdx.x * 256 + threadIdx.x) >> 5;
    const int nwarps = gridDim.x * 8;
    const float gam = gamma[0];

    float ps0[4] = {0, 0, 0, 0}, ps1[4] = {0, 0, 0, 0};
    float pq0[4] = {0, 0, 0, 0}, pq1[4] = {0, 0, 0, 0};

    for (int node = gwarp; node < N_NODES; node += nwarps) {
        const float4* hd = (const float4*)(g_h1 + (long)node * HID);
        float4 d0 = hd[lane], d1 = hd[lane + 32];
        float4 a0 = make_float4(0.f, 0.f, 0.f, 0.f);
        float4 a1 = make_float4(0.f, 0.f, 0.f, 0.f);
        float den = 0.f;
        const int beg = g_off[node];
        const int cnt = g_cnt[node];

        float4 s0, s1;
        if (cnt > 0) {
            int sn = g_csr_src[beg];
            const float4* hp = (const float4*)(g_h1 + (long)sn * HID);
            s0 = hp[lane]; s1 = hp[lane + 32];
        }
        for (int e = 0; e < cnt; e++) {
            float4 c0 = s0, c1 = s1;
            if (e + 1 < cnt) {
                int sn = g_csr_src[beg + e + 1];
                const float4* hp = (const float4*)(g_h1 + (long)sn * HID);
                s0 = hp[lane]; s1 = hp[lane + 32];
            }
            float dx = c0.x - d0.x; float d2 = dx * dx;
            dx = c0.y - d0.y; d2 = fmaf(dx, dx, d2);
            dx = c0.z - d0.z; d2 = fmaf(dx, dx, d2);
            dx = c0.w - d0.w; d2 = fmaf(dx, dx, d2);
            dx = c1.x - d1.x; d2 = fmaf(dx, dx, d2);
            dx = c1.y - d1.y; d2 = fmaf(dx, dx, d2);
            dx = c1.z - d1.z; d2 = fmaf(dx, dx, d2);
            dx = c1.w - d1.w; d2 = fmaf(dx, dx, d2);
            #pragma unroll
            for (int o = 16; o > 0; o >>= 1) d2 += __shfl_xor_sync(0xffffffffu, d2, o);
            float w = __expf(-gam * d2);
            a0.x = fmaf(w, c0.x, a0.x); a0.y = fmaf(w, c0.y, a0.y);
            a0.z = fmaf(w, c0.z, a0.z); a0.w = fmaf(w, c0.w, a0.w);
            a1.x = fmaf(w, c1.x, a1.x); a1.y = fmaf(w, c1.y, a1.y);
            a1.z = fmaf(w, c1.z, a1.z); a1.w = fmaf(w, c1.w, a1.w);
            den += w;
        }
        float inv = 1.f / (den + 1e-16f);
        float4 x0 = make_float4(a0.x * inv, a0.y * inv, a0.z * inv, a0.w * inv);
        float4 x1 = make_float4(a1.x * inv, a1.y * inv, a1.z * inv, a1.w * inv);
        float4* xp = (float4*)(g_x1 + (long)node * HID);
        xp[lane] = x0; xp[lane + 32] = x1;
        ps0[0] += x0.x; ps0[1] += x0.y; ps0[2] += x0.z; ps0[3] += x0.w;
        ps1[0] += x1.x; ps1[1] += x1.y; ps1[2] += x1.z; ps1[3] += x1.w;
        pq0[0] += x0.x * x0.x; pq0[1] += x0.y * x0.y; pq0[2] += x0.z * x0.z; pq0[3] += x0.w * x0.w;
        pq1[0] += x1.x * x1.x; pq1[1] += x1.y * x1.y; pq1[2] += x1.z * x1.z; pq1[3] += x1.w * x1.w;
    }

    __shared__ float sm_s[HID], sm_q[HID];
    sm_s[threadIdx.x] = 0.f; sm_q[threadIdx.x] = 0.f;
    __syncthreads();
    #pragma unroll
    for (int j = 0; j < 4; j++) {
        atomicAdd(&sm_s[4 * lane + j], ps0[j]);
        atomicAdd(&sm_s[128 + 4 * lane + j], ps1[j]);
        atomicAdd(&sm_q[4 * lane + j], pq0[j]);
        atomicAdd(&sm_q[128 + 4 * lane + j], pq1[j]);
    }
    __syncthreads();
    atomicAdd(&g_sum1[threadIdx.x], sm_s[threadIdx.x]);
    atomicAdd(&g_sq1[threadIdx.x], sm_q[threadIdx.x]);
}

__global__ void bnprep1_kernel(const float* __restrict__ w, const float* __restrict__ b) {
    int c = threadIdx.x;
    float mean = g_sum1[c] * (1.f / N_NODES);
    float var  = g_sq1[c] * (1.f / N_NODES) - mean * mean;
    float sc = w[c] * rsqrtf(var + 1e-5f);
    g_scale1[c] = sc;
    g_shift1[c] = b[c] - mean * sc;
}

// ---------------- GEMM2 (tensor cores): h2 = relu(bn1(x1)) @ W2 + b2 ---------------
__global__ __launch_bounds__(256) void gemm2_tc_kernel(const float* __restrict__ b2) {
    __shared__ float s_sc[HID], s_sh[HID];
    if (threadIdx.x < 128) {
        s_sc[threadIdx.x] = g_scale1[threadIdx.x];
        s_sc[threadIdx.x + 128] = g_scale1[threadIdx.x + 128];
        s_sh[threadIdx.x] = g_shift1[threadIdx.x];
        s_sh[threadIdx.x + 128] = g_shift1[threadIdx.x + 128];
    }
    __syncthreads();

    const int w = threadIdx.x >> 5, lane = threadIdx.x & 31;
    const int g = lane >> 2, i = lane & 3;
    const int m_base = blockIdx.x * 512 + w * 64;

    float acc[4][5][4];
    #pragma unroll
    for (int mi = 0; mi < 4; mi++)
        #pragma unroll
        for (int ni = 0; ni < 5; ni++)
            #pragma unroll
            for (int r = 0; r < 4; r++) acc[mi][ni][r] = 0.f;

    #pragma unroll 1
    for (int kt = 0; kt < 16; kt++) {
        const int c0 = kt * 16 + 2 * i;
        float sc0 = s_sc[c0], sc1 = s_sc[c0 + 1], sc8 = s_sc[c0 + 8], sc9 = s_sc[c0 + 9];
        float sh0 = s_sh[c0], sh1 = s_sh[c0 + 1], sh8 = s_sh[c0 + 8], sh9 = s_sh[c0 + 9];

        uint2 bh[5], bl[5];
        #pragma unroll
        for (int ni = 0; ni < 5; ni++) {
            int t = (kt * 5 + ni) * 32 + lane;
            bh[ni] = g_w2_hi[t];
            bl[ni] = g_w2_lo[t];
        }

        uint4 ah[4], al[4];
        #pragma unroll
        for (int mi = 0; mi < 4; mi++) {
            int r0 = min(m_base + mi * 16 + g, N_NODES - 1);
            int r1 = min(m_base + mi * 16 + g + 8, N_NODES - 1);
            const float* p0 = g_x1 + (long)r0 * HID + c0;
            const float* p1 = g_x1 + (long)r1 * HID + c0;
            float2 u0 = *(const float2*)p0;
            float2 u2 = *(const float2*)(p0 + 8);
            float2 u1 = *(const float2*)p1;
            float2 u3 = *(const float2*)(p1 + 8);
            u0.x = fmaxf(fmaf(u0.x, sc0, sh0), 0.f);
            u0.y = fmaxf(fmaf(u0.y, sc1, sh1), 0.f);
            u1.x = fmaxf(fmaf(u1.x, sc0, sh0), 0.f);
            u1.y = fmaxf(fmaf(u1.y, sc1, sh1), 0.f);
            u2.x = fmaxf(fmaf(u2.x, sc8, sh8), 0.f);
            u2.y = fmaxf(fmaf(u2.y, sc9, sh9), 0.f);
            u3.x = fmaxf(fmaf(u3.x, sc8, sh8), 0.f);
            u3.y = fmaxf(fmaf(u3.y, sc9, sh9), 0.f);
            split2(u0.x, u0.y, ah[mi].x, al[mi].x);
            split2(u1.x, u1.y, ah[mi].y, al[mi].y);
            split2(u2.x, u2.y, ah[mi].z, al[mi].z);
            split2(u3.x, u3.y, ah[mi].w, al[mi].w);
        }

        #pragma unroll
        for (int mi = 0; mi < 4; mi++)
            #pragma unroll
            for (int ni = 0; ni < 5; ni++) {
                MMA_BF16(acc[mi][ni], ah[mi], bh[ni]);
                MMA_BF16(acc[mi][ni], ah[mi], bl[ni]);
                MMA_BF16(acc[mi][ni], al[mi], bh[ni]);
            }
    }

    #pragma unroll
    for (int mi = 0; mi < 4; mi++) {
        int r0 = m_base + mi * 16 + g;
        int r1 = r0 + 8;
        #pragma unroll
        for (int ni = 0; ni < 5; ni++) {
            int c = ni * 8 + 2 * i;
            float bx = b2[c], by = b2[c + 1];
            if (r0 < N_NODES) {
                float2 o = make_float2(acc[mi][ni][0] + bx, acc[mi][ni][1] + by);
                *(float2*)&g_h2[(long)r0 * OUT + c] = o;
            }
            if (r1 < N_NODES) {
                float2 o = make_float2(acc[mi][ni][2] + bx, acc[mi][ni][3] + by);
                *(float2*)&g_h2[(long)r1 * OUT + c] = o;
            }
        }
    }
}

// ---------------- Layer-2 aggregation (prefetch depth 1) --------------------------
__global__ __launch_bounds__(256) void agg2_kernel(const float* __restrict__ gamma) {
    const int lane = threadIdx.x & 31;
    const int gwarp = (blockIdx.x * 256 + threadIdx.x) >> 5;
    const int nwarps = gridDim.x * 8;
    const float gam = gamma[0];

    float ps[2] = {0, 0}, pq[2] = {0, 0};

    for (int node = gwarp; node < N_NODES; node += nwarps) {
        const float2* hd = (const float2*)(g_h2 + (long)node * OUT);
        float2 d = make_float2(0.f, 0.f);
        if (lane < 20) d = hd[lane];
        float2 a = make_float2(0.f, 0.f);
        float den = 0.f;
        const int beg = g_off[node];
        const int cnt = g_cnt[node];

        float2 sv = make_float2(0.f, 0.f);
        if (cnt > 0) {
            int sn = g_csr_src[beg];
            if (lane < 20) sv = ((const float2*)(g_h2 + (long)sn * OUT))[lane];
        }
        for (int e = 0; e < cnt; e++) {
            float2 c = sv;
            if (e + 1 < cnt) {
                int sn = g_csr_src[beg + e + 1];
                if (lane < 20) sv = ((const float2*)(g_h2 + (long)sn * OUT))[lane];
            }
            float dx = c.x - d.x, dy = c.y - d.y;
            float d2 = (lane < 20) ? fmaf(dx, dx, dy * dy) : 0.f;
            #pragma unroll
            for (int o = 16; o > 0; o >>= 1) d2 += __shfl_xor_sync(0xffffffffu, d2, o);
            float w = __expf(-gam * d2);
            a.x = fmaf(w, c.x, a.x); a.y = fmaf(w, c.y, a.y);
            den += w;
        }
        float inv = 1.f / (den + 1e-16f);
        float2 x = make_float2(a.x * inv, a.y * inv);
        if (lane < 20) {
            ((float2*)(g_x2 + (long)node * OUT))[lane] = x;
            ps[0] += x.x; ps[1] += x.y;
            pq[0] += x.x * x.x; pq[1] += x.y * x.y;
        }
    }

    __shared__ float sm_s[OUT], sm_q[OUT];
    if (threadIdx.x < OUT) { sm_s[threadIdx.x] = 0.f; sm_q[threadIdx.x] = 0.f; }
    __syncthreads();
    if (lane < 20) {
        atomicAdd(&sm_s[2 * lane + 0], ps[0]);
        atomicAdd(&sm_s[2 * lane + 1], ps[1]);
        atomicAdd(&sm_q[2 * lane + 0], pq[0]);
        atomicAdd(&sm_q[2 * lane + 1], pq[1]);
    }
    __syncthreads();
    if (threadIdx.x < OUT) {
        atomicAdd(&g_sum2[threadIdx.x], sm_s[threadIdx.x]);
        atomicAdd(&g_sq2[threadIdx.x], sm_q[threadIdx.x]);
    }
}

__global__ void bnprep2_kernel(const float* __restrict__ w, const float* __restrict__ b) {
    int c = threadIdx.x;
    float mean = g_sum2[c] * (1.f / N_NODES);
    float var  = g_sq2[c] * (1.f / N_NODES) - mean * mean;
    float sc = w[c] * rsqrtf(var + 1e-5f);
    g_scale2[c] = sc;
    g_shift2[c] = b[c] - mean * sc;
}

// ---------------- gather batch nodes, BN2 + relu + log_softmax -------------------
__global__ __launch_bounds__(256) void final_kernel(
    const void* __restrict__ bnodes, float* __restrict__ out)
{
    int warp = (blockIdx.x * 256 + threadIdx.x) >> 5;
    int lane = threadIdx.x & 31;
    if (warp >= N_BATCH) return;
    int node = load_idx(bnodes, warp);
    const float* x = g_x2 + (long)node * OUT;

    float v0 = fmaxf(fmaf(x[lane], g_scale2[lane], g_shift2[lane]), 0.f);
    float v1 = -1e30f;
    if (lane < 8)
        v1 = fmaxf(fmaf(x[32 + lane], g_scale2[32 + lane], g_shift2[32 + lane]), 0.f);

    float m = fmaxf(v0, v1);
    #pragma unroll
    for (int o = 16; o > 0; o >>= 1) m = fmaxf(m, __shfl_xor_sync(0xffffffffu, m, o));
    float e = expf(v0 - m) + (lane < 8 ? expf(v1 - m) : 0.f);
    #pragma unroll
    for (int o = 16; o > 0; o >>= 1) e += __shfl_xor_sync(0xffffffffu, e, o);
    float lz = m + logf(e);

    out[(long)warp * OUT + lane] = v0 - lz;
    if (lane < 8) out[(long)warp * OUT + 32 + lane] = v1 - lz;
}

// ---------------- launcher --------------------------------------------------------
extern "C" void kernel_launch(void* const* d_in, const int* in_sizes, int n_in,
                              void* d_out, int out_size) {
    const float* features = (const float*)d_in[0];
    const void*  edge     = d_in[1];
    const void*  batch    = d_in[2];
    const float* W1 = (const float*)d_in[3];
    const float* b1 = (const float*)d_in[4];
    const float* g1 = (const float*)d_in[5];
    const float* W2 = (const float*)d_in[6];
    const float* b2 = (const float*)d_in[7];
    const float* g2 = (const float*)d_in[8];
    const float* bn1w = (const float*)d_in[9];
    const float* bn1b = (const float*)d_in[10];
    const float* bn2w = (const float*)d_in[11];
    const float* bn2b = (const float*)d_in[12];
    float* out = (float*)d_out;

    // persistent side-stream + fork/join events (created on the uncaptured
    // correctness call; reused identically on the capture call)
    static cudaStream_t s2 = 0;
    static cudaEvent_t ev_fork = 0, ev_join = 0;
    if (!s2) {
        cudaStreamCreateWithFlags(&s2, cudaStreamNonBlocking);
        cudaEventCreateWithFlags(&ev_fork, cudaEventDisableTiming);
        cudaEventCreateWithFlags(&ev_join, cudaEventDisableTiming);
    }

    detect_zero_kernel<<<NB_SCAN, 256>>>(edge);
    cudaEventRecord(ev_fork, 0);

    // ---- side stream: CSR build (independent of the GEMM chain) ----
    cudaStreamWaitEvent(s2, ev_fork, 0);
    hist_kernel<<<(N_EDGES + 255) / 256, 256, 0, s2>>>(edge);
    scan1_kernel<<<NB_SCAN, 256, 0, s2>>>();
    scan2_kernel<<<1, 256, 0, s2>>>();
    scan3_kernel<<<NB_SCAN, 256, 0, s2>>>();
    scatter_kernel<<<(N_EDGES + 255) / 256, 256, 0, s2>>>(edge);
    cudaEventRecord(ev_join, s2);

    // ---- main stream: weight prep + GEMM1 ----
    prepW_kernel<<<(16 * 32 * 32 + 255) / 256, 256>>>(W1);
    prepW2_kernel<<<(16 * 5 * 32 + 255) / 256, 256>>>(W2);
    dim3 gg1((N_NODES + 127) / 128, 2);
    gemm1_tc_kernel<<<gg1, 256>>>(features, b1);

    // join: agg1 needs both gemm1 (main) and CSR (side)
    cudaStreamWaitEvent(0, ev_join, 0);

    agg1_kernel<<<2048, 256>>>(g1);
    bnprep1_kernel<<<1, HID>>>(bn1w, bn1b);

    gemm2_tc_kernel<<<(N_NODES + 511) / 512, 256>>>(b2);
    agg2_kernel<<<1024, 256>>>(g2);
    bnprep2_kernel<<<1, OUT>>>(bn2w, bn2b);

    final_kernel<<<(N_BATCH * 32 + 255) / 256, 256>>>(batch, out);
}